// round 8
// baseline (speedup 1.0000x reference)
#include <cuda_runtime.h>
#include <mma.h>
using namespace nvcuda;

// Problem constants (fixed by the benchmark)
#define NN     50000
#define KK     10
#define K1     11
#define EMAX   800000
#define NTHR   256
#define RT     64
#define NTILES 782        // ceil(50000/64)
#define CBLK   148        // cold-path persistent blocks (one wave)
#define LDSM   68         // padded smem row stride (floats)
#define BUF    (64 * LDSM)   // floats per plane (17408 B)

// dynamic smem planes: A=Xhi/Hhi, B=Xlo/Hlo, WH, WL, E (mma output staging)
#define P_A   0
#define P_B   1
#define P_WH  2
#define P_WL  3
#define P_E   4
#define DYNSMEM (5 * BUF * 4)   // 87040 B -> 2 blocks/SM

// ---------------- device scratch (static, zero-initialized) ----------------
__device__ float g_wE[EMAX];
__device__ int   g_deg[NN];
__device__ float g_dinv[NN];
__device__ float g_y0[NN * 64];
__device__ float g_y1[NN * 64];
__device__ float g_acc[NN * 64];
__device__ float g_h[NN * 64];
__device__ unsigned g_bar_cnt;
__device__ volatile unsigned g_bar_gen;

__device__ __constant__ float c_binom[K1][K1] = {
    {1,0,0,0,0,0,0,0,0,0,0},
    {1,1,0,0,0,0,0,0,0,0,0},
    {1,2,1,0,0,0,0,0,0,0,0},
    {1,3,3,1,0,0,0,0,0,0,0},
    {1,4,6,4,1,0,0,0,0,0,0},
    {1,5,10,10,5,1,0,0,0,0,0},
    {1,6,15,20,15,6,1,0,0,0,0},
    {1,7,21,35,35,21,7,1,0,0,0},
    {1,8,28,56,70,56,28,8,1,0,0},
    {1,9,36,84,126,126,84,36,9,1,0},
    {1,10,45,120,210,252,210,120,45,10,1}
};

typedef wmma::fragment<wmma::accumulator, 16, 16, 8, float> AccFrag;

// ---------------------------- helpers ---------------------------------------
__device__ __forceinline__ void tf32split(float v, float &hi, float &lo) {
    unsigned u;
    asm("cvt.rna.tf32.f32 %0, %1;" : "=r"(u) : "f"(v));
    hi = __uint_as_float(u);
    float r = v - hi;
    asm("cvt.rna.tf32.f32 %0, %1;" : "=r"(u) : "f"(r));
    lo = __uint_as_float(u);
}

// ---------------------------------------------------------------------------
// Grid barrier over exactly CBLK blocks (cold path only).
// ---------------------------------------------------------------------------
__device__ __forceinline__ void gbar() {
    __syncthreads();
    if (threadIdx.x == 0) {
        unsigned gen = g_bar_gen;
        __threadfence();
        if (atomicAdd(&g_bar_cnt, 1u) == CBLK - 1u) {
            g_bar_cnt = 0u;
            __threadfence();
            g_bar_gen = gen + 1u;
        } else {
            while (g_bar_gen == gen) { }
            __threadfence();
        }
    }
    __syncthreads();
}

// ---------------------------------------------------------------------------
// Gated polynomial propagation: g_acc = sum_m a_m A^m xin (COO atomics).
// ---------------------------------------------------------------------------
__device__ void poly_phase(const float* __restrict__ xin,
                           const int* __restrict__ src,
                           const int* __restrict__ dst,
                           int e, int gt, int gsz, const float* sa) {
    float a0v = sa[0];
    for (int i = gt; i < NN * 64; i += gsz) g_acc[i] = a0v * xin[i];
    const float* yin = xin;
    float* yout = g_y0;
    float* yoth = g_y1;
    for (int m = 1; m <= KK; m++) {
        for (int i = gt; i < NN * 64; i += gsz) yout[i] = 0.0f;
        gbar();
        int tot = e * 32;
        for (int t = gt; t < tot; t += gsz) {
            int ed = t >> 5;
            int l = (t & 31) << 1;
            float w = g_wE[ed];
            int s = src[ed], d = dst[ed];
            float2 v = *(const float2*)(yin + s * 64 + l);
            atomicAdd(&yout[d * 64 + l],     w * v.x);
            atomicAdd(&yout[d * 64 + l + 1], w * v.y);
        }
        gbar();
        float am = sa[m];
        for (int i = gt; i < NN * 64; i += gsz) g_acc[i] += am * yout[i];
        yin = yout;
        float* t2 = yout; yout = yoth; yoth = t2;
    }
    gbar();
}

// ---------------------------------------------------------------------------
// Staging: split fp32 into tf32 hi/lo planes in smem (float4 granularity).
// ---------------------------------------------------------------------------
__device__ __forceinline__ void stage_x_split(const float* __restrict__ X, int row0,
                                              float* xh, float* xl, int tid) {
#pragma unroll
    for (int it = 0; it < 4; it++) {
        int q = tid + it * NTHR;
        int row = q >> 4, c4 = (q & 15) << 2;
        int gr = row0 + row;
        if (gr >= NN) gr = NN - 1;
        float4 v = *(const float4*)(X + gr * 64 + c4);
        float4 h4, l4;
        tf32split(v.x, h4.x, l4.x);
        tf32split(v.y, h4.y, l4.y);
        tf32split(v.z, h4.z, l4.z);
        tf32split(v.w, h4.w, l4.w);
        *(float4*)(xh + row * LDSM + c4) = h4;
        *(float4*)(xl + row * LDSM + c4) = l4;
    }
}
__device__ __forceinline__ void stage_w_split(const float* __restrict__ W, float s,
                                              float* wh, float* wl, int tid) {
#pragma unroll
    for (int it = 0; it < 4; it++) {
        int q = tid + it * NTHR;
        int k = q >> 4, c4 = (q & 15) << 2;
        float4 v = *(const float4*)(W + k * 64 + c4);
        float4 h4, l4;
        tf32split(v.x * s, h4.x, l4.x);
        tf32split(v.y * s, h4.y, l4.y);
        tf32split(v.z * s, h4.z, l4.z);
        tf32split(v.w * s, h4.w, l4.w);
        *(float4*)(wh + k * LDSM + c4) = h4;
        *(float4*)(wl + k * LDSM + c4) = l4;
    }
}

// ---------------------------------------------------------------------------
// 64x64x64 3xTF32 GEMM: acc (2 tiles per warp) += A @ B. No smem writes.
// ---------------------------------------------------------------------------
__device__ __forceinline__ void mma2tiles(const float* Ah, const float* Al,
                                          const float* Bh, const float* Bl,
                                          int warp, AccFrag acc[2]) {
#pragma unroll
    for (int i = 0; i < 2; i++) {
        int t = warp * 2 + i;
        int tr = t >> 2, tc = t & 3;
        wmma::fill_fragment(acc[i], 0.0f);
#pragma unroll
        for (int k = 0; k < 8; k++) {
            wmma::fragment<wmma::matrix_a, 16, 16, 8, wmma::precision::tf32, wmma::row_major> ah, al;
            wmma::fragment<wmma::matrix_b, 16, 16, 8, wmma::precision::tf32, wmma::row_major> bh, bl;
            wmma::load_matrix_sync(ah, Ah + tr * 16 * LDSM + k * 8, LDSM);
            wmma::load_matrix_sync(al, Al + tr * 16 * LDSM + k * 8, LDSM);
            wmma::load_matrix_sync(bh, Bh + k * 8 * LDSM + tc * 16, LDSM);
            wmma::load_matrix_sync(bl, Bl + k * 8 * LDSM + tc * 16, LDSM);
            wmma::mma_sync(acc[i], ah, bh, acc[i]);
            wmma::mma_sync(acc[i], al, bh, acc[i]);
            wmma::mma_sync(acc[i], ah, bl, acc[i]);
        }
    }
}
__device__ __forceinline__ void store2tiles(float* E, int warp, AccFrag acc[2]) {
#pragma unroll
    for (int i = 0; i < 2; i++) {
        int t = warp * 2 + i;
        int tr = t >> 2, tc = t & 3;
        wmma::store_matrix_sync(E + tr * 16 * LDSM + tc * 16, acc[i], LDSM,
                                wmma::mem_row_major);
    }
}

// ---------------------------------------------------------------------------
// Kernel.
// ---------------------------------------------------------------------------
__global__ __launch_bounds__(NTHR, 2) void bernnet(
    const float* __restrict__ x,
    const int*   __restrict__ src,
    const int*   __restrict__ dst,
    int e,
    const float* __restrict__ coe,
    const float* __restrict__ W1, const float* __restrict__ b1,
    const float* __restrict__ W2, const float* __restrict__ b2,
    const float* __restrict__ fcw, const float* __restrict__ fcb,
    float* __restrict__ out)
{
    extern __shared__ __align__(16) float dsm[];
    float* A  = dsm + P_A  * BUF;
    float* B  = dsm + P_B  * BUF;
    float* WH = dsm + P_WH * BUF;
    float* WL = dsm + P_WL * BUF;
    float* E  = dsm + P_E  * BUF;
    __shared__ float s_a[K1];
    __shared__ int   s_need;

    const int tid  = threadIdx.x;
    const int warp = tid >> 5;

    // ---- Bernstein -> monomial coefficients (exact dyadic; per-block) ----
    if (tid < 32) {
        int m = tid;
        float a = 0.0f;
        if (m <= KK) {
            for (int j = 0; j <= KK; j++) {
                float cj = coe[j];
                cj = cj > 0.0f ? cj : 0.0f;
                float Bv = 0.0f;
                for (int p = 0; p <= j && p <= m; p++) {
                    int q = m - p;
                    if (q > KK - j) continue;
                    float t = c_binom[j][p] * c_binom[KK - j][q];
                    Bv += (p & 1) ? -t : t;
                }
                a += cj * (c_binom[KK][j] * (1.0f / 1024.0f)) * Bv;
            }
            s_a[m] = a;
        }
        unsigned msk = __ballot_sync(0xffffffffu, (m >= 1 && m <= KK && a != 0.0f));
        if (m == 0) s_need = msk ? 1 : 0;
    }
    __syncthreads();
    const int need = s_need;

    if (!need) {
        // ================= fast path: p(A) = a0*I ==========================
        const float a0 = s_a[0];
        const int row0 = blockIdx.x * RT;

        stage_x_split(x, row0, A, B, tid);
        stage_w_split(W1, a0, WH, WL, tid);
        __syncthreads();

        AccFrag acc[2];
        // ---- layer 1: acc = X @ (a0*W1) ----
        mma2tiles(A, B, WH, WL, warp, acc);
        __syncthreads();          // all reads of A,B,WH,WL complete
        store2tiles(E, warp, acc);
        stage_w_split(W2, a0, WH, WL, tid);   // overwrite W planes with W2
        __syncthreads();

        // ---- H = relu(E + b1), tf32-split back into A,B planes ----
        {
            const int c = tid & 63;
            const float b = b1[c];
#pragma unroll
            for (int it = 0; it < 16; it++) {
                int row = (tid + it * NTHR) >> 6;
                float hv = fmaxf(E[row * LDSM + c] + b, 0.0f);
                float hi, lo;
                tf32split(hv, hi, lo);
                A[row * LDSM + c] = hi;
                B[row * LDSM + c] = lo;
            }
        }
        __syncthreads();

        // ---- layer 2: acc = H @ (a0*W2) ----
        mma2tiles(A, B, WH, WL, warp, acc);
        __syncthreads();
        store2tiles(E, warp, acc);
        __syncthreads();

        // ---- fc: out[row] = sum_c relu(E + b2[c]) * fcw[c] + fcb ----
        {
            const int row = tid >> 2, q = tid & 3;
            float s = 0.0f;
#pragma unroll
            for (int j = 0; j < 16; j++) {
                int c = q * 16 + j;
                s += fmaxf(E[row * LDSM + c] + b2[c], 0.0f) * fcw[c];
            }
            s += __shfl_xor_sync(0xffffffffu, s, 1);
            s += __shfl_xor_sync(0xffffffffu, s, 2);
            int g = row0 + row;
            if (q == 0 && g < NN) out[g] = s + fcb[0];
        }
        return;
    }

    // ================= cold path: full polynomial semantics =================
    if (blockIdx.x >= CBLK) return;
    const int gt  = blockIdx.x * NTHR + tid;
    const int gsz = CBLK * NTHR;

    for (int i = gt; i < NN; i += gsz) g_deg[i] = 0;
    gbar();
    for (int t = gt; t < e; t += gsz) atomicAdd(&g_deg[src[t]], 1);
    gbar();
    for (int i = gt; i < NN; i += gsz) {
        int d = g_deg[i];
        g_dinv[i] = d > 0 ? rsqrtf((float)d) : 0.0f;
    }
    gbar();
    for (int t = gt; t < e; t += gsz) g_wE[t] = g_dinv[src[t]] * g_dinv[dst[t]];
    gbar();

    poly_phase(x, src, dst, e, gt, gsz, s_a);

    // layer-1 pass: g_h = relu(g_acc @ W1 + b1)
    stage_w_split(W1, 1.0f, WH, WL, tid);
    for (int t = blockIdx.x; t < NTILES; t += CBLK) {
        __syncthreads();
        stage_x_split(g_acc, t * RT, A, B, tid);
        __syncthreads();
        AccFrag acc[2];
        mma2tiles(A, B, WH, WL, warp, acc);
        __syncthreads();
        store2tiles(E, warp, acc);
        __syncthreads();
        const int c = tid & 63;
        const float b = b1[c];
#pragma unroll
        for (int it = 0; it < 16; it++) {
            int row = (tid + it * NTHR) >> 6;
            int g = t * RT + row;
            if (g < NN)
                g_h[g * 64 + c] = fmaxf(E[row * LDSM + c] + b, 0.0f);
        }
    }
    gbar();

    poly_phase(g_h, src, dst, e, gt, gsz, s_a);

    // layer-2 + fc pass
    stage_w_split(W2, 1.0f, WH, WL, tid);
    for (int t = blockIdx.x; t < NTILES; t += CBLK) {
        __syncthreads();
        stage_x_split(g_acc, t * RT, A, B, tid);
        __syncthreads();
        AccFrag acc[2];
        mma2tiles(A, B, WH, WL, warp, acc);
        __syncthreads();
        store2tiles(E, warp, acc);
        __syncthreads();
        const int row = tid >> 2, q = tid & 3;
        float s = 0.0f;
#pragma unroll
        for (int j = 0; j < 16; j++) {
            int c = q * 16 + j;
            s += fmaxf(E[row * LDSM + c] + b2[c], 0.0f) * fcw[c];
        }
        s += __shfl_xor_sync(0xffffffffu, s, 1);
        s += __shfl_xor_sync(0xffffffffu, s, 2);
        int g = t * RT + row;
        if (q == 0 && g < NN) out[g] = s + fcb[0];
    }
}

// ---------------------------------------------------------------------------
extern "C" void kernel_launch(void* const* d_in, const int* in_sizes, int n_in,
                              void* d_out, int out_size) {
    const float* x   = (const float*)d_in[0];
    const int*   ei  = (const int*)d_in[1];
    const float* coe = (const float*)d_in[2];
    const float* W1  = (const float*)d_in[3];
    const float* b1  = (const float*)d_in[4];
    const float* W2  = (const float*)d_in[5];
    const float* b2  = (const float*)d_in[6];
    const float* fcw = (const float*)d_in[7];
    const float* fcb = (const float*)d_in[8];
    float* out = (float*)d_out;

    int e = in_sizes[1] / 2;
    const int* src = ei;
    const int* dst = ei + e;

    static int smem_set = 0;
    if (!smem_set) {
        cudaFuncSetAttribute(bernnet, cudaFuncAttributeMaxDynamicSharedMemorySize,
                             DYNSMEM);
        smem_set = 1;
    }

    bernnet<<<NTILES, NTHR, DYNSMEM>>>(x, src, dst, e, coe,
                                       W1, b1, W2, b2, fcw, fcb, out);
}

// round 9
// speedup vs baseline: 1.4857x; 1.4857x over previous
#include <cuda_runtime.h>
#include <mma.h>
using namespace nvcuda;

// Problem constants (fixed by the benchmark)
#define NN     50000
#define KK     10
#define K1     11
#define EMAX   800000
#define NTHR   256
#define RT     64
#define NTILES 782        // ceil(50000/64)
#define CBLK   148        // cold-path persistent blocks (one wave)
#define LDSM   68         // padded smem row stride (floats)
#define BUF    (64 * LDSM)   // floats per plane (17408 B)

// fast kernel planes: XH XL W1H W1L W2H W2L  (C1/H/C2 reuse XH/XL in place)
#define DYNSMEM_FAST (6 * BUF * 4)   // 104448 B -> 2 blocks/SM
// cold kernel planes: A B WH WL E
#define DYNSMEM_COLD (5 * BUF * 4)   // 87040 B

// ---------------- device scratch (static, zero-initialized) ----------------
__device__ float g_wE[EMAX];
__device__ int   g_deg[NN];
__device__ float g_dinv[NN];
__device__ float g_y0[NN * 64];
__device__ float g_y1[NN * 64];
__device__ float g_acc[NN * 64];
__device__ float g_h[NN * 64];
__device__ unsigned g_bar_cnt;
__device__ volatile unsigned g_bar_gen;

__device__ __constant__ float c_binom[K1][K1] = {
    {1,0,0,0,0,0,0,0,0,0,0},
    {1,1,0,0,0,0,0,0,0,0,0},
    {1,2,1,0,0,0,0,0,0,0,0},
    {1,3,3,1,0,0,0,0,0,0,0},
    {1,4,6,4,1,0,0,0,0,0,0},
    {1,5,10,10,5,1,0,0,0,0,0},
    {1,6,15,20,15,6,1,0,0,0,0},
    {1,7,21,35,35,21,7,1,0,0,0},
    {1,8,28,56,70,56,28,8,1,0,0},
    {1,9,36,84,126,126,84,36,9,1,0},
    {1,10,45,120,210,252,210,120,45,10,1}
};

typedef wmma::fragment<wmma::accumulator, 16, 16, 8, float> AccFrag;

// ---------------------------- helpers ---------------------------------------
__device__ __forceinline__ void tf32split(float v, float &hi, float &lo) {
    unsigned u;
    asm("cvt.rna.tf32.f32 %0, %1;" : "=r"(u) : "f"(v));
    hi = __uint_as_float(u);
    float r = v - hi;
    asm("cvt.rna.tf32.f32 %0, %1;" : "=r"(u) : "f"(r));
    lo = __uint_as_float(u);
}

// Bernstein -> monomial coefficients (exact dyadic arithmetic); tid<32 lanes.
__device__ __forceinline__ void compute_coeffs(const float* __restrict__ coe,
                                               float* s_a, int* s_need, int tid) {
    if (tid < 32) {
        int m = tid;
        float a = 0.0f;
        if (m <= KK) {
            for (int j = 0; j <= KK; j++) {
                float cj = coe[j];
                cj = cj > 0.0f ? cj : 0.0f;
                float Bv = 0.0f;
                for (int p = 0; p <= j && p <= m; p++) {
                    int q = m - p;
                    if (q > KK - j) continue;
                    float t = c_binom[j][p] * c_binom[KK - j][q];
                    Bv += (p & 1) ? -t : t;
                }
                a += cj * (c_binom[KK][j] * (1.0f / 1024.0f)) * Bv;
            }
            s_a[m] = a;
        }
        unsigned msk = __ballot_sync(0xffffffffu, (m >= 1 && m <= KK && a != 0.0f));
        if (m == 0) *s_need = msk ? 1 : 0;
    }
}

// Staging: split fp32 into tf32 hi/lo planes in smem (float4 granularity).
__device__ __forceinline__ void stage_x_split(const float* __restrict__ X, int row0,
                                              float* xh, float* xl, int tid) {
#pragma unroll
    for (int it = 0; it < 4; it++) {
        int q = tid + it * NTHR;
        int row = q >> 4, c4 = (q & 15) << 2;
        int gr = row0 + row;
        if (gr >= NN) gr = NN - 1;
        float4 v = *(const float4*)(X + gr * 64 + c4);
        float4 h4, l4;
        tf32split(v.x, h4.x, l4.x);
        tf32split(v.y, h4.y, l4.y);
        tf32split(v.z, h4.z, l4.z);
        tf32split(v.w, h4.w, l4.w);
        *(float4*)(xh + row * LDSM + c4) = h4;
        *(float4*)(xl + row * LDSM + c4) = l4;
    }
}
__device__ __forceinline__ void stage_w_split(const float* __restrict__ W, float s,
                                              float* wh, float* wl, int tid) {
#pragma unroll
    for (int it = 0; it < 4; it++) {
        int q = tid + it * NTHR;
        int k = q >> 4, c4 = (q & 15) << 2;
        float4 v = *(const float4*)(W + k * 64 + c4);
        float4 h4, l4;
        tf32split(v.x * s, h4.x, l4.x);
        tf32split(v.y * s, h4.y, l4.y);
        tf32split(v.z * s, h4.z, l4.z);
        tf32split(v.w * s, h4.w, l4.w);
        *(float4*)(wh + k * LDSM + c4) = h4;
        *(float4*)(wl + k * LDSM + c4) = l4;
    }
}

// 64x64x64 3xTF32 GEMM: acc (2 tiles per warp) = A @ B. No smem writes.
__device__ __forceinline__ void mma2tiles(const float* Ah, const float* Al,
                                          const float* Bh, const float* Bl,
                                          int warp, AccFrag acc[2]) {
#pragma unroll
    for (int i = 0; i < 2; i++) {
        int t = warp * 2 + i;
        int tr = t >> 2, tc = t & 3;
        wmma::fill_fragment(acc[i], 0.0f);
#pragma unroll 2
        for (int k = 0; k < 8; k++) {
            wmma::fragment<wmma::matrix_a, 16, 16, 8, wmma::precision::tf32, wmma::row_major> ah, al;
            wmma::fragment<wmma::matrix_b, 16, 16, 8, wmma::precision::tf32, wmma::row_major> bh, bl;
            wmma::load_matrix_sync(ah, Ah + tr * 16 * LDSM + k * 8, LDSM);
            wmma::load_matrix_sync(al, Al + tr * 16 * LDSM + k * 8, LDSM);
            wmma::load_matrix_sync(bh, Bh + k * 8 * LDSM + tc * 16, LDSM);
            wmma::load_matrix_sync(bl, Bl + k * 8 * LDSM + tc * 16, LDSM);
            wmma::mma_sync(acc[i], ah, bh, acc[i]);
            wmma::mma_sync(acc[i], al, bh, acc[i]);
            wmma::mma_sync(acc[i], ah, bl, acc[i]);
        }
    }
}
__device__ __forceinline__ void store2tiles(float* E, int warp, AccFrag acc[2]) {
#pragma unroll
    for (int i = 0; i < 2; i++) {
        int t = warp * 2 + i;
        int tr = t >> 2, tc = t & 3;
        wmma::store_matrix_sync(E + tr * 16 * LDSM + tc * 16, acc[i], LDSM,
                                wmma::mem_row_major);
    }
}

// ===========================================================================
// FAST kernel: p(A) = a0*I path only. One 64-row tile per block.
// Lean register budget -> 2 blocks/SM, no cold-path pressure.
// ===========================================================================
__global__ __launch_bounds__(NTHR, 2) void bernnet_fast(
    const float* __restrict__ x,
    const float* __restrict__ coe,
    const float* __restrict__ W1, const float* __restrict__ b1,
    const float* __restrict__ W2, const float* __restrict__ b2,
    const float* __restrict__ fcw, const float* __restrict__ fcb,
    float* __restrict__ out)
{
    extern __shared__ __align__(16) float dsm[];
    float* XH  = dsm;
    float* XL  = dsm + 1 * BUF;
    float* W1H = dsm + 2 * BUF;
    float* W1L = dsm + 3 * BUF;
    float* W2H = dsm + 4 * BUF;
    float* W2L = dsm + 5 * BUF;
    __shared__ float s_a[K1];
    __shared__ int   s_need;

    const int tid  = threadIdx.x;
    const int warp = tid >> 5;

    compute_coeffs(coe, s_a, &s_need, tid);
    __syncthreads();
    if (s_need) return;                 // cold kernel owns this case

    const float a0 = s_a[0];
    const int row0 = blockIdx.x * RT;

    stage_x_split(x, row0, XH, XL, tid);
    stage_w_split(W1, a0, W1H, W1L, tid);
    stage_w_split(W2, a0, W2H, W2L, tid);
    __syncthreads();

    AccFrag acc[2];
    // ---- layer 1: acc = X @ (a0*W1) ----
    mma2tiles(XH, XL, W1H, W1L, warp, acc);
    __syncthreads();                    // all reads of XH/XL complete
    store2tiles(XH, warp, acc);         // C1 -> XH plane
    __syncthreads();

    // ---- H = relu(C1 + b1), tf32-split in place (hi->XH, lo->XL) ----
    {
        const int c = tid & 63;
        const float b = b1[c];
#pragma unroll
        for (int it = 0; it < 16; it++) {
            int row = (tid + it * NTHR) >> 6;
            float hv = fmaxf(XH[row * LDSM + c] + b, 0.0f);
            float hi, lo;
            tf32split(hv, hi, lo);
            XH[row * LDSM + c] = hi;
            XL[row * LDSM + c] = lo;
        }
    }
    __syncthreads();

    // ---- layer 2: acc = H @ (a0*W2) ----
    mma2tiles(XH, XL, W2H, W2L, warp, acc);
    __syncthreads();
    store2tiles(XH, warp, acc);         // C2 -> XH plane
    __syncthreads();

    // ---- fc: out[row] = sum_c relu(C2 + b2[c]) * fcw[c] + fcb ----
    {
        const int row = tid >> 2, q = tid & 3;
        float s = 0.0f;
#pragma unroll
        for (int j = 0; j < 16; j++) {
            int c = q * 16 + j;
            s += fmaxf(XH[row * LDSM + c] + b2[c], 0.0f) * fcw[c];
        }
        s += __shfl_xor_sync(0xffffffffu, s, 1);
        s += __shfl_xor_sync(0xffffffffu, s, 2);
        int g = row0 + row;
        if (q == 0 && g < NN) out[g] = s + fcb[0];
    }
}

// ===========================================================================
// COLD kernel: full polynomial semantics (arbitrary coe). 148 persistent
// blocks with grid barriers. Returns immediately when p(A) = a0*I.
// ===========================================================================
__device__ __forceinline__ void gbar() {
    __syncthreads();
    if (threadIdx.x == 0) {
        unsigned gen = g_bar_gen;
        __threadfence();
        if (atomicAdd(&g_bar_cnt, 1u) == CBLK - 1u) {
            g_bar_cnt = 0u;
            __threadfence();
            g_bar_gen = gen + 1u;
        } else {
            while (g_bar_gen == gen) { }
            __threadfence();
        }
    }
    __syncthreads();
}

__device__ void poly_phase(const float* __restrict__ xin,
                           const int* __restrict__ src,
                           const int* __restrict__ dst,
                           int e, int gt, int gsz, const float* sa) {
    float a0v = sa[0];
    for (int i = gt; i < NN * 64; i += gsz) g_acc[i] = a0v * xin[i];
    const float* yin = xin;
    float* yout = g_y0;
    float* yoth = g_y1;
    for (int m = 1; m <= KK; m++) {
        for (int i = gt; i < NN * 64; i += gsz) yout[i] = 0.0f;
        gbar();
        int tot = e * 32;
        for (int t = gt; t < tot; t += gsz) {
            int ed = t >> 5;
            int l = (t & 31) << 1;
            float w = g_wE[ed];
            int s = src[ed], d = dst[ed];
            float2 v = *(const float2*)(yin + s * 64 + l);
            atomicAdd(&yout[d * 64 + l],     w * v.x);
            atomicAdd(&yout[d * 64 + l + 1], w * v.y);
        }
        gbar();
        float am = sa[m];
        for (int i = gt; i < NN * 64; i += gsz) g_acc[i] += am * yout[i];
        yin = yout;
        float* t2 = yout; yout = yoth; yoth = t2;
    }
    gbar();
}

__global__ __launch_bounds__(NTHR) void bernnet_cold(
    const float* __restrict__ x,
    const int*   __restrict__ src,
    const int*   __restrict__ dst,
    int e,
    const float* __restrict__ coe,
    const float* __restrict__ W1, const float* __restrict__ b1,
    const float* __restrict__ W2, const float* __restrict__ b2,
    const float* __restrict__ fcw, const float* __restrict__ fcb,
    float* __restrict__ out)
{
    extern __shared__ __align__(16) float dsm[];
    float* A  = dsm;
    float* B  = dsm + 1 * BUF;
    float* WH = dsm + 2 * BUF;
    float* WL = dsm + 3 * BUF;
    float* E  = dsm + 4 * BUF;
    __shared__ float s_a[K1];
    __shared__ int   s_need;

    const int tid  = threadIdx.x;
    const int warp = tid >> 5;

    compute_coeffs(coe, s_a, &s_need, tid);
    __syncthreads();
    if (!s_need) return;                // fast kernel owns this case

    const int gt  = blockIdx.x * NTHR + tid;
    const int gsz = CBLK * NTHR;

    for (int i = gt; i < NN; i += gsz) g_deg[i] = 0;
    gbar();
    for (int t = gt; t < e; t += gsz) atomicAdd(&g_deg[src[t]], 1);
    gbar();
    for (int i = gt; i < NN; i += gsz) {
        int d = g_deg[i];
        g_dinv[i] = d > 0 ? rsqrtf((float)d) : 0.0f;
    }
    gbar();
    for (int t = gt; t < e; t += gsz) g_wE[t] = g_dinv[src[t]] * g_dinv[dst[t]];
    gbar();

    poly_phase(x, src, dst, e, gt, gsz, s_a);

    // layer-1 pass: g_h = relu(g_acc @ W1 + b1)
    stage_w_split(W1, 1.0f, WH, WL, tid);
    for (int t = blockIdx.x; t < NTILES; t += CBLK) {
        __syncthreads();
        stage_x_split(g_acc, t * RT, A, B, tid);
        __syncthreads();
        AccFrag acc[2];
        mma2tiles(A, B, WH, WL, warp, acc);
        __syncthreads();
        store2tiles(E, warp, acc);
        __syncthreads();
        const int c = tid & 63;
        const float b = b1[c];
#pragma unroll
        for (int it = 0; it < 16; it++) {
            int row = (tid + it * NTHR) >> 6;
            int g = t * RT + row;
            if (g < NN)
                g_h[g * 64 + c] = fmaxf(E[row * LDSM + c] + b, 0.0f);
        }
    }
    gbar();

    poly_phase(g_h, src, dst, e, gt, gsz, s_a);

    // layer-2 + fc pass
    stage_w_split(W2, 1.0f, WH, WL, tid);
    for (int t = blockIdx.x; t < NTILES; t += CBLK) {
        __syncthreads();
        stage_x_split(g_acc, t * RT, A, B, tid);
        __syncthreads();
        AccFrag acc[2];
        mma2tiles(A, B, WH, WL, warp, acc);
        __syncthreads();
        store2tiles(E, warp, acc);
        __syncthreads();
        const int row = tid >> 2, q = tid & 3;
        float s = 0.0f;
#pragma unroll
        for (int j = 0; j < 16; j++) {
            int c = q * 16 + j;
            s += fmaxf(E[row * LDSM + c] + b2[c], 0.0f) * fcw[c];
        }
        s += __shfl_xor_sync(0xffffffffu, s, 1);
        s += __shfl_xor_sync(0xffffffffu, s, 2);
        int g = t * RT + row;
        if (q == 0 && g < NN) out[g] = s + fcb[0];
    }
}

// ---------------------------------------------------------------------------
extern "C" void kernel_launch(void* const* d_in, const int* in_sizes, int n_in,
                              void* d_out, int out_size) {
    const float* x   = (const float*)d_in[0];
    const int*   ei  = (const int*)d_in[1];
    const float* coe = (const float*)d_in[2];
    const float* W1  = (const float*)d_in[3];
    const float* b1  = (const float*)d_in[4];
    const float* W2  = (const float*)d_in[5];
    const float* b2  = (const float*)d_in[6];
    const float* fcw = (const float*)d_in[7];
    const float* fcb = (const float*)d_in[8];
    float* out = (float*)d_out;

    int e = in_sizes[1] / 2;
    const int* src = ei;
    const int* dst = ei + e;

    static int smem_set = 0;
    if (!smem_set) {
        cudaFuncSetAttribute(bernnet_fast, cudaFuncAttributeMaxDynamicSharedMemorySize,
                             DYNSMEM_FAST);
        cudaFuncSetAttribute(bernnet_cold, cudaFuncAttributeMaxDynamicSharedMemorySize,
                             DYNSMEM_COLD);
        smem_set = 1;
    }

    bernnet_fast<<<NTILES, NTHR, DYNSMEM_FAST>>>(x, coe, W1, b1, W2, b2,
                                                 fcw, fcb, out);
    bernnet_cold<<<CBLK, NTHR, DYNSMEM_COLD>>>(x, src, dst, e, coe,
                                               W1, b1, W2, b2, fcw, fcb, out);
}

// round 10
// speedup vs baseline: 2.2669x; 1.5258x over previous
#include <cuda_runtime.h>

// Problem constants (fixed by the benchmark)
#define NN     50000
#define KK     10
#define K1     11
#define EMAX   800000
#define NTHR   512
#define RT     64
#define NTILES 782        // ceil(50000/64)
#define CBLK   148        // cold-path persistent blocks

// dynamic smem layout (bytes)
#define S_X    0u         // X/H tile: 64 rows x 256B (swizzled)
#define S_WA1  16384u     // W1 plane A: 16 k4 x 32 cp x 16B
#define S_WB1  24576u     // W1 plane B
#define S_WA2  32768u     // W2 plane A
#define S_WB2  40960u     // W2 plane B
#define S_RED  49152u     // fc reduction: 64 rows x 8 warpC floats
#define DYNSMEM (49152 + 2048)

typedef unsigned long long ull;

// ---------------- device scratch (static, zero-initialized) ----------------
__device__ float g_wE[EMAX];
__device__ int   g_deg[NN];
__device__ float g_dinv[NN];
__device__ float g_y0[NN * 64];
__device__ float g_y1[NN * 64];
__device__ float g_acc[NN * 64];
__device__ float g_h[NN * 64];
__device__ unsigned g_bar_cnt;
__device__ volatile unsigned g_bar_gen;

__device__ __constant__ float c_binom[K1][K1] = {
    {1,0,0,0,0,0,0,0,0,0,0},
    {1,1,0,0,0,0,0,0,0,0,0},
    {1,2,1,0,0,0,0,0,0,0,0},
    {1,3,3,1,0,0,0,0,0,0,0},
    {1,4,6,4,1,0,0,0,0,0,0},
    {1,5,10,10,5,1,0,0,0,0,0},
    {1,6,15,20,15,6,1,0,0,0,0},
    {1,7,21,35,35,21,7,1,0,0,0},
    {1,8,28,56,70,56,28,8,1,0,0},
    {1,9,36,84,126,126,84,36,9,1,0},
    {1,10,45,120,210,252,210,120,45,10,1}
};

// ---------------------------- PTX helpers -----------------------------------
__device__ __forceinline__ ull ffma2(ull a, ull b, ull c) {
    ull d;
    asm("fma.rn.f32x2 %0, %1, %2, %3;" : "=l"(d) : "l"(a), "l"(b), "l"(c));
    return d;
}
__device__ __forceinline__ ull pack2(float lo, float hi) {
    ull d;
    asm("mov.b64 %0, {%1, %2};" : "=l"(d) : "f"(lo), "f"(hi));
    return d;
}
__device__ __forceinline__ float hsum2(ull v) {
    float a, b;
    asm("mov.b64 {%0, %1}, %2;" : "=f"(a), "=f"(b) : "l"(v));
    return a + b;
}
__device__ __forceinline__ void lds_2x64(ull &a, ull &b, unsigned addr) {
    asm volatile("ld.shared.v2.u64 {%0, %1}, [%2];" : "=l"(a), "=l"(b) : "r"(addr));
}
__device__ __forceinline__ void sts64(unsigned addr, ull v) {
    asm volatile("st.shared.u64 [%0], %1;" :: "r"(addr), "l"(v) : "memory");
}
__device__ __forceinline__ void sts_v4(unsigned addr, float a, float b, float c, float d) {
    asm volatile("st.shared.v4.f32 [%0], {%1, %2, %3, %4};"
                 :: "r"(addr), "f"(a), "f"(b), "f"(c), "f"(d) : "memory");
}
__device__ __forceinline__ void cp16(unsigned dst, const float* src) {
    asm volatile("cp.async.ca.shared.global [%0], [%1], 16;" :: "r"(dst), "l"(src) : "memory");
}

// ---------------------------------------------------------------------------
// Bernstein -> monomial coefficients (exact dyadic arithmetic); tid<32 lanes.
// ---------------------------------------------------------------------------
__device__ __forceinline__ void compute_coeffs(const float* __restrict__ coe,
                                               float* s_a, int* s_need, int tid) {
    if (tid < 32) {
        int m = tid;
        float a = 0.0f;
        if (m <= KK) {
            for (int j = 0; j <= KK; j++) {
                float cj = coe[j];
                cj = cj > 0.0f ? cj : 0.0f;
                float Bv = 0.0f;
                for (int p = 0; p <= j && p <= m; p++) {
                    int q = m - p;
                    if (q > KK - j) continue;
                    float t = c_binom[j][p] * c_binom[KK - j][q];
                    Bv += (p & 1) ? -t : t;
                }
                a += cj * (c_binom[KK][j] * (1.0f / 1024.0f)) * Bv;
            }
            s_a[m] = a;
        }
        unsigned msk = __ballot_sync(0xffffffffu, (m >= 1 && m <= KK && a != 0.0f));
        if (m == 0) *s_need = msk ? 1 : 0;
    }
}

// ---------------------------------------------------------------------------
// Staging.
// X tile: row-major 256B rows; 16B chunk ch stored at ch' = ch ^ (row & 7).
// W planes: for (k4, cp): Wa 16B = {W[4k4][2cp],W[4k4+1][2cp],W[4k4][2cp+1],
//           W[4k4+1][2cp+1]}, Wb same for k rows 4k4+2, 4k4+3.
// ---------------------------------------------------------------------------
__device__ __forceinline__ void stage_x(const float* __restrict__ X, int row0,
                                        unsigned sxb, int tid) {
#pragma unroll
    for (int it = 0; it < 2; it++) {
        int q = tid + it * NTHR;
        int row = q >> 4, ch = q & 15;
        int gr = row0 + row;
        if (gr >= NN) gr = NN - 1;
        unsigned d = sxb + row * 256 + ((ch ^ (row & 7)) << 4);
        cp16(d, X + gr * 64 + ch * 4);
    }
}
__device__ __forceinline__ void stage_w(const float* __restrict__ W, float s,
                                        unsigned wa, unsigned wb, int tid) {
    int k4 = tid >> 5, cp = tid & 31;
    const float* p = W + (4 * k4) * 64 + 2 * cp;
    float w00 = p[0]   * s, w01 = p[1]   * s;   // k = 4k4
    float w10 = p[64]  * s, w11 = p[65]  * s;   // k = 4k4+1
    float w20 = p[128] * s, w21 = p[129] * s;   // k = 4k4+2
    float w30 = p[192] * s, w31 = p[193] * s;   // k = 4k4+3
    sts_v4(wa + k4 * 512 + cp * 16, w00, w10, w01, w11);
    sts_v4(wb + k4 * 512 + cp * 16, w20, w30, w21, w31);
}

// ---------------------------------------------------------------------------
// 64x64 tile GEMM core: thread computes 4 rows x 2 cols (k-paired acc[8]).
// xbase: this thread's row-0 base; xswz = lanesR<<4; rr stride 2048B.
// wa/wb: this thread's cp offset already folded in (cp*16).
// ---------------------------------------------------------------------------
__device__ __forceinline__ void core64(unsigned xbase, unsigned xswz,
                                       unsigned wa, unsigned wb, ull acc[8]) {
#pragma unroll
    for (int i = 0; i < 8; i++) acc[i] = 0ull;
#pragma unroll
    for (int k4 = 0; k4 < 16; k4++) {
        unsigned xo = xbase + (((unsigned)(k4 << 4)) ^ xswz);
        unsigned wo = (unsigned)(k4 << 9);
        ull x01[4], x23[4];
#pragma unroll
        for (int r = 0; r < 4; r++) lds_2x64(x01[r], x23[r], xo + r * 2048);
        ull wa0, wa1, wb0, wb1;
        lds_2x64(wa0, wa1, wa + wo);
        lds_2x64(wb0, wb1, wb + wo);
#pragma unroll
        for (int r = 0; r < 4; r++) {
            acc[r * 2 + 0] = ffma2(x01[r], wa0, acc[r * 2 + 0]);
            acc[r * 2 + 1] = ffma2(x01[r], wa1, acc[r * 2 + 1]);
            acc[r * 2 + 0] = ffma2(x23[r], wb0, acc[r * 2 + 0]);
            acc[r * 2 + 1] = ffma2(x23[r], wb1, acc[r * 2 + 1]);
        }
    }
}

// ---------------------------------------------------------------------------
// Cold-path machinery (__noinline__: spills under the 64-reg cap are fine
// here — this path only runs for coe values that keep the polynomial).
// ---------------------------------------------------------------------------
__device__ __forceinline__ void gbar() {
    __syncthreads();
    if (threadIdx.x == 0) {
        unsigned gen = g_bar_gen;
        __threadfence();
        if (atomicAdd(&g_bar_cnt, 1u) == CBLK - 1u) {
            g_bar_cnt = 0u;
            __threadfence();
            g_bar_gen = gen + 1u;
        } else {
            while (g_bar_gen == gen) { }
            __threadfence();
        }
    }
    __syncthreads();
}

__device__ __noinline__ void poly_phase(const float* __restrict__ xin,
                                        const int* __restrict__ src,
                                        const int* __restrict__ dst,
                                        int e, int gt, int gsz, const float* sa) {
    float a0v = sa[0];
    for (int i = gt; i < NN * 64; i += gsz) g_acc[i] = a0v * xin[i];
    const float* yin = xin;
    float* yout = g_y0;
    float* yoth = g_y1;
    for (int m = 1; m <= KK; m++) {
        for (int i = gt; i < NN * 64; i += gsz) yout[i] = 0.0f;
        gbar();
        int tot = e * 32;
        for (int t = gt; t < tot; t += gsz) {
            int ed = t >> 5;
            int l = (t & 31) << 1;
            float w = g_wE[ed];
            int s = src[ed], d = dst[ed];
            float2 v = *(const float2*)(yin + s * 64 + l);
            atomicAdd(&yout[d * 64 + l],     w * v.x);
            atomicAdd(&yout[d * 64 + l + 1], w * v.y);
        }
        gbar();
        float am = sa[m];
        for (int i = gt; i < NN * 64; i += gsz) g_acc[i] += am * yout[i];
        yin = yout;
        float* t2 = yout; yout = yoth; yoth = t2;
    }
    gbar();
}

__device__ __noinline__ void cold_path(
    const float* x, const int* src, const int* dst, int e,
    const float* W1, const float* b1,
    const float* W2, const float* b2,
    const float* fcw, const float* fcb,
    float* out, const float* s_a, unsigned sb, float* sred)
{
    const int tid  = threadIdx.x;
    const int gt   = blockIdx.x * NTHR + tid;
    const int gsz  = CBLK * NTHR;
    const int lane = tid & 31;
    const int warp = tid >> 5;
    const int warpR = warp >> 3, warpC = warp & 7;
    const int lanesR = lane >> 2, lanesC = lane & 3;
    const int cp = warpC * 4 + lanesC;
    const int c0 = 2 * cp;
    const unsigned xbase = sb + S_X + (warpR * 32 + lanesR) * 256;
    const unsigned xswz  = (unsigned)(lanesR << 4);
    const unsigned wa1 = sb + S_WA1 + cp * 16, wb1 = sb + S_WB1 + cp * 16;
    const unsigned wa2 = sb + S_WA2 + cp * 16, wb2 = sb + S_WB2 + cp * 16;

    for (int i = gt; i < NN; i += gsz) g_deg[i] = 0;
    gbar();
    for (int t = gt; t < e; t += gsz) atomicAdd(&g_deg[src[t]], 1);
    gbar();
    for (int i = gt; i < NN; i += gsz) {
        int d = g_deg[i];
        g_dinv[i] = d > 0 ? rsqrtf((float)d) : 0.0f;
    }
    gbar();
    for (int t = gt; t < e; t += gsz) g_wE[t] = g_dinv[src[t]] * g_dinv[dst[t]];
    gbar();

    poly_phase(x, src, dst, e, gt, gsz, s_a);

    // layer 1: g_h = relu(g_acc @ W1 + b1)
    stage_w(W1, 1.0f, sb + S_WA1, sb + S_WB1, tid);
    const float2 b1v = *(const float2*)(b1 + c0);
    for (int t = blockIdx.x; t < NTILES; t += CBLK) {
        __syncthreads();
        stage_x(g_acc, t * RT, sb + S_X, tid);
        asm volatile("cp.async.commit_group;\n\tcp.async.wait_group 0;" ::: "memory");
        __syncthreads();
        ull acc[8];
        core64(xbase, xswz, wa1, wb1, acc);
#pragma unroll
        for (int rr = 0; rr < 4; rr++) {
            int row = warpR * 32 + rr * 8 + lanesR;
            int g = t * RT + row;
            if (g < NN) {
                float2 hv;
                hv.x = fmaxf(hsum2(acc[rr * 2 + 0]) + b1v.x, 0.0f);
                hv.y = fmaxf(hsum2(acc[rr * 2 + 1]) + b1v.y, 0.0f);
                *(float2*)(g_h + g * 64 + c0) = hv;
            }
        }
    }
    gbar();

    poly_phase(g_h, src, dst, e, gt, gsz, s_a);

    // layer 2 + fc
    stage_w(W2, 1.0f, sb + S_WA2, sb + S_WB2, tid);
    const float2 b2v = *(const float2*)(b2 + c0);
    const float2 fwv = *(const float2*)(fcw + c0);
    const float  fb  = fcb[0];
    for (int t = blockIdx.x; t < NTILES; t += CBLK) {
        __syncthreads();
        stage_x(g_acc, t * RT, sb + S_X, tid);
        asm volatile("cp.async.commit_group;\n\tcp.async.wait_group 0;" ::: "memory");
        __syncthreads();
        ull acc[8];
        core64(xbase, xswz, wa2, wb2, acc);
        float pv[4];
#pragma unroll
        for (int rr = 0; rr < 4; rr++) {
            pv[rr] = fmaxf(hsum2(acc[rr * 2 + 0]) + b2v.x, 0.0f) * fwv.x
                   + fmaxf(hsum2(acc[rr * 2 + 1]) + b2v.y, 0.0f) * fwv.y;
            pv[rr] += __shfl_xor_sync(0xffffffffu, pv[rr], 1);
            pv[rr] += __shfl_xor_sync(0xffffffffu, pv[rr], 2);
        }
        if (lanesC == 0)
#pragma unroll
            for (int rr = 0; rr < 4; rr++)
                sred[(warpR * 32 + rr * 8 + lanesR) * 8 + warpC] = pv[rr];
        __syncthreads();
        if (tid < RT) {
            const float4* rp = (const float4*)sred + tid * 2;
            float4 a4 = rp[0], b4 = rp[1];
            int g = t * RT + tid;
            if (g < NN)
                out[g] = a4.x + a4.y + a4.z + a4.w + b4.x + b4.y + b4.z + b4.w + fb;
        }
    }
}

// ---------------------------------------------------------------------------
// Kernel. Fast path (p(A)=a0*I): one 64-row tile per block, fully fused,
// 64-reg footprint -> 2 blocks/SM (32 warps).
// ---------------------------------------------------------------------------
__global__ __launch_bounds__(NTHR, 2) void bernnet(
    const float* __restrict__ x,
    const int*   __restrict__ src,
    const int*   __restrict__ dst,
    int e,
    const float* __restrict__ coe,
    const float* __restrict__ W1, const float* __restrict__ b1,
    const float* __restrict__ W2, const float* __restrict__ b2,
    const float* __restrict__ fcw, const float* __restrict__ fcb,
    float* __restrict__ out)
{
    extern __shared__ __align__(16) char dsm[];
    const unsigned sb = (unsigned)__cvta_generic_to_shared(dsm);
    float* sred = (float*)(dsm + S_RED);
    __shared__ float s_a[K1];
    __shared__ int   s_need;

    const int tid = threadIdx.x;

    compute_coeffs(coe, s_a, &s_need, tid);
    __syncthreads();

    if (s_need) {
        if (blockIdx.x < CBLK)
            cold_path(x, src, dst, e, W1, b1, W2, b2, fcw, fcb, out, s_a, sb, sred);
        return;
    }

    // ===================== fast path: p(A) = a0*I ==========================
    const float a0 = s_a[0];
    const int row0 = blockIdx.x * RT;

    const int lane  = tid & 31;
    const int warp  = tid >> 5;
    const int warpR = warp >> 3, warpC = warp & 7;
    const int lanesR = lane >> 2, lanesC = lane & 3;
    const int cp = warpC * 4 + lanesC;
    const int c0 = 2 * cp;

    const unsigned xbase = sb + S_X + (warpR * 32 + lanesR) * 256;
    const unsigned xswz  = (unsigned)(lanesR << 4);
    const unsigned wa1 = sb + S_WA1 + cp * 16, wb1 = sb + S_WB1 + cp * 16;
    const unsigned wa2 = sb + S_WA2 + cp * 16, wb2 = sb + S_WB2 + cp * 16;
    // H store base (H reuses the X plane, same swizzled layout)
    const unsigned hstore = sb + S_X + (warpR * 32 + lanesR) * 256
                          + ((((unsigned)(cp >> 1)) ^ (unsigned)lanesR) << 4)
                          + ((c0 & 3) << 2);

    stage_x(x, row0, sb + S_X, tid);
    asm volatile("cp.async.commit_group;" ::: "memory");
    stage_w(W1, a0, sb + S_WA1, sb + S_WB1, tid);
    stage_w(W2, a0, sb + S_WA2, sb + S_WB2, tid);
    const float2 b1v = *(const float2*)(b1 + c0);
    const float2 b2v = *(const float2*)(b2 + c0);
    const float2 fwv = *(const float2*)(fcw + c0);
    const float  fb  = fcb[0];
    asm volatile("cp.async.wait_group 0;" ::: "memory");
    __syncthreads();

    ull acc[8];
    // ---- GEMM1: acc = (a0*x) @ W1 ----
    core64(xbase, xswz, wa1, wb1, acc);
    __syncthreads();                 // all X reads complete before overwrite

    // ---- H = relu(acc + b1) into X plane ----
#pragma unroll
    for (int rr = 0; rr < 4; rr++) {
        float h0 = fmaxf(hsum2(acc[rr * 2 + 0]) + b1v.x, 0.0f);
        float h1 = fmaxf(hsum2(acc[rr * 2 + 1]) + b1v.y, 0.0f);
        sts64(hstore + rr * 2048, pack2(h0, h1));
    }
    __syncthreads();

    // ---- GEMM2: acc = H @ (a0*W2) ----
    core64(xbase, xswz, wa2, wb2, acc);

    // ---- fc: out = relu(acc + b2) . fcw + fcb ----
    float pv[4];
#pragma unroll
    for (int rr = 0; rr < 4; rr++) {
        pv[rr] = fmaxf(hsum2(acc[rr * 2 + 0]) + b2v.x, 0.0f) * fwv.x
               + fmaxf(hsum2(acc[rr * 2 + 1]) + b2v.y, 0.0f) * fwv.y;
        pv[rr] += __shfl_xor_sync(0xffffffffu, pv[rr], 1);
        pv[rr] += __shfl_xor_sync(0xffffffffu, pv[rr], 2);
    }
    if (lanesC == 0)
#pragma unroll
        for (int rr = 0; rr < 4; rr++)
            sred[(warpR * 32 + rr * 8 + lanesR) * 8 + warpC] = pv[rr];
    __syncthreads();
    if (tid < RT) {
        const float4* rp = (const float4*)sred + tid * 2;
        float4 a4 = rp[0], b4 = rp[1];
        int g = row0 + tid;
        if (g < NN)
            out[g] = a4.x + a4.y + a4.z + a4.w + b4.x + b4.y + b4.z + b4.w + fb;
    }
}

// ---------------------------------------------------------------------------
extern "C" void kernel_launch(void* const* d_in, const int* in_sizes, int n_in,
                              void* d_out, int out_size) {
    const float* x   = (const float*)d_in[0];
    const int*   ei  = (const int*)d_in[1];
    const float* coe = (const float*)d_in[2];
    const float* W1  = (const float*)d_in[3];
    const float* b1  = (const float*)d_in[4];
    const float* W2  = (const float*)d_in[5];
    const float* b2  = (const float*)d_in[6];
    const float* fcw = (const float*)d_in[7];
    const float* fcb = (const float*)d_in[8];
    float* out = (float*)d_out;

    int e = in_sizes[1] / 2;
    const int* src = ei;
    const int* dst = ei + e;

    static int smem_set = 0;
    if (!smem_set) {
        cudaFuncSetAttribute(bernnet, cudaFuncAttributeMaxDynamicSharedMemorySize,
                             DYNSMEM);
        smem_set = 1;
    }

    bernnet<<<NTILES, NTHR, DYNSMEM>>>(x, src, dst, e, coe,
                                       W1, b1, W2, b2, fcw, fcb, out);
}